// round 14
// baseline (speedup 1.0000x reference)
#include <cuda_runtime.h>
#include <cstdint>

#define B_ 8
#define V_ 49
#define H_ 128
#define W_ 128
#define F_ 64

// out[b,v,h,f] = sum_w lfi[b,v,h,w] + W * h_mask[b,f,h]
//
// 256-bit-load kernel: one ld.v8 (1KB/warp) covers TWO h-rows of one (b,v);
// one st.v4 (512B/warp) covers the two matching output rows.
// Block = (b, h-pair, v-half): grid 1024 = one wave at 7 blocks/SM, 224 thr.

__device__ __forceinline__ float ld256_sum8(const float* a) {
    unsigned r0, r1, r2, r3, r4, r5, r6, r7;
    asm volatile(
        "ld.global.L2::evict_last.v8.b32 {%0,%1,%2,%3,%4,%5,%6,%7}, [%8];"
        : "=r"(r0), "=r"(r1), "=r"(r2), "=r"(r3),
          "=r"(r4), "=r"(r5), "=r"(r6), "=r"(r7)
        : "l"(a));
    const float s01 = __uint_as_float(r0) + __uint_as_float(r1);
    const float s23 = __uint_as_float(r2) + __uint_as_float(r3);
    const float s45 = __uint_as_float(r4) + __uint_as_float(r5);
    const float s67 = __uint_as_float(r6) + __uint_as_float(r7);
    return (s01 + s23) + (s45 + s67);
}
__device__ __forceinline__ unsigned long long pol_evict_first() {
    unsigned long long p;
    asm("createpolicy.fractional.L2::evict_first.b64 %0, 1.0;" : "=l"(p));
    return p;
}
__device__ __forceinline__ void st_ef4(float4* a, float4 v, unsigned long long pol) {
    asm volatile("st.global.L2::cache_hint.v4.f32 [%0], {%1,%2,%3,%4}, %5;"
                 :: "l"(a), "f"(v.x), "f"(v.y), "f"(v.z), "f"(v.w), "l"(pol)
                 : "memory");
}

template <int ILP>
__device__ __forceinline__ void run_rows(
    const float* __restrict__ lfi, float4* __restrict__ out4,
    const float* __restrict__ m_s, int bv0, int h0, int wid, int lane,
    unsigned long long pf)
{
    // bv0 = b*49 + first v of this warp; v-stride 1; rows 2 per v via h-pair.
    float s[ILP];
    #pragma unroll
    for (int j = 0; j < ILP; j++) {
        const size_t base = ((size_t)(bv0 + j) * H_ + h0) * W_;  // float offset
        s[j] = ld256_sum8(lfi + base + lane * 8);
    }
    // 4-stage butterfly: lanes 0-15 -> row h0 sum, lanes 16-31 -> row h0+1 sum
    #pragma unroll
    for (int o = 8; o > 0; o >>= 1) {
        #pragma unroll
        for (int j = 0; j < ILP; j++)
            s[j] += __shfl_xor_sync(0xffffffffu, s[j], o);
    }
    // Mask float4 per lane: m_s laid out [h-of-pair][64f]; lane maps directly.
    const float4 m = ((const float4*)m_s)[lane];
    #pragma unroll
    for (int j = 0; j < ILP; j++) {
        // out rows (bv0+j, h0) and (bv0+j, h0+1) are contiguous: 32 float4s
        const size_t o4 = ((size_t)(bv0 + j) * H_ + h0) * (F_ / 4);
        st_ef4(&out4[o4 + lane],
               make_float4(s[j] + m.x, s[j] + m.y, s[j] + m.z, s[j] + m.w), pf);
    }
}

__global__ void __launch_bounds__(224, 7)
depth_cue_kernel(const float* __restrict__ lfi,
                 const float* __restrict__ h_mask,
                 float4* __restrict__ out4) {
    __shared__ float m_s[2 * F_];   // [h-of-pair][f]

    const int tid  = threadIdx.x;
    const int wid  = tid >> 5;
    const int lane = tid & 31;

    // blockIdx.x = ((b*64) + hp)*2 + vhalf
    const int vhalf = blockIdx.x & 1;
    const int bhp   = blockIdx.x >> 1;
    const int b     = bhp >> 6;
    const int h0    = (bhp & 63) << 1;          // even h, pair (h0, h0+1)

    // Mask gather for both rows of the pair, issued first (overlaps lfi loads):
    // tid<128: f = tid>>1, hh = tid&1 -> adjacent addresses per pair.
    if (tid < 2 * F_) {
        const int f  = tid >> 1;
        const int hh = tid & 1;
        m_s[hh * F_ + f] =
            (float)W_ * __ldg(&h_mask[((b << 6) + f) * H_ + h0 + hh]);
    }
    __syncthreads();

    const unsigned long long pf = pol_evict_first();

    if (vhalf == 0) {
        // v in [0,28): warp w handles v = 4w..4w+3 (ILP 4)
        run_rows<4>(lfi, out4, m_s, b * V_ + wid * 4, h0, wid, lane, pf);
    } else {
        // v in [28,49): warp w handles v = 28+3w..28+3w+2 (ILP 3)
        run_rows<3>(lfi, out4, m_s, b * V_ + 28 + wid * 3, h0, wid, lane, pf);
    }
}

extern "C" void kernel_launch(void* const* d_in, const int* in_sizes, int n_in,
                              void* d_out, int out_size) {
    // Identify inputs by element count (robust to ordering):
    //   lfi    : B*V*H*W = 6,422,528
    //   f_maps : B*H*W*F = 8,388,608 (dead input — never touched)
    //   h_mask : B*F*H   = 65,536
    const float* lfi = nullptr;
    const float* h_mask = nullptr;
    for (int i = 0; i < n_in; i++) {
        if (in_sizes[i] == B_ * V_ * H_ * W_) lfi = (const float*)d_in[i];
        else if (in_sizes[i] == B_ * F_ * H_) h_mask = (const float*)d_in[i];
    }

    // grid = 8 b * 64 h-pairs * 2 v-halves = 1024 blocks, 224 threads
    depth_cue_kernel<<<1024, 224>>>(lfi, h_mask, (float4*)d_out);
}

// round 15
// speedup vs baseline: 1.0938x; 1.0938x over previous
#include <cuda_runtime.h>

// Problem constants
#define B_ 8
#define V_ 49
#define H_ 128
#define W_ 128
#define F_ 64

// out[b,v,h,f] = sum_w lfi[b,v,h,w] + W * h_mask[b,f,h]
//
// Champion structure (R13): block = one (b,h) pair, 1024 blocks, 7 warps x 7
// v-rows, smem mask staging (minimal L1tex wavefronts for the scattered mask),
// deferred sync, L2 residency steering (lfi evict_last, out evict_first).
// This round: min-blocks 8 (was 7) -> 56 resident warps/SM, one extra block
// prologue in flight per SM; still a single wave (148*8 = 1184 >= 1024).

__device__ __forceinline__ unsigned long long pol_evict_first() {
    unsigned long long p;
    asm("createpolicy.fractional.L2::evict_first.b64 %0, 1.0;" : "=l"(p));
    return p;
}
__device__ __forceinline__ unsigned long long pol_evict_last() {
    unsigned long long p;
    asm("createpolicy.fractional.L2::evict_last.b64 %0, 1.0;" : "=l"(p));
    return p;
}
__device__ __forceinline__ float4 ld_keep4(const float4* a, unsigned long long pol) {
    float4 v;
    asm volatile("ld.global.L2::cache_hint.v4.f32 {%0,%1,%2,%3}, [%4], %5;"
                 : "=f"(v.x), "=f"(v.y), "=f"(v.z), "=f"(v.w)
                 : "l"(a), "l"(pol));
    return v;
}
__device__ __forceinline__ void st_stream2(float2* a, float x, float y,
                                           unsigned long long pol) {
    asm volatile("st.global.L2::cache_hint.v2.f32 [%0], {%1,%2}, %3;"
                 :: "l"(a), "f"(x), "f"(y), "l"(pol) : "memory");
}

__global__ void __launch_bounds__(224, 8)
depth_cue_kernel(const float4* __restrict__ lfi4,
                 const float* __restrict__ h_mask,
                 float2* __restrict__ out2) {
    __shared__ float m_s[F_];

    const int tid  = threadIdx.x;
    const int wid  = tid >> 5;
    const int lane = tid & 31;

    const int pair = blockIdx.x;          // b*128 + h
    const int b = pair >> 7;
    const int h = pair & (H_ - 1);

    const unsigned long long pl = pol_evict_last();
    const unsigned long long pf = pol_evict_first();

    // 1) Scattered mask gather (warps 0,1 only), issued first to overlap lfi loads
    float mval = 0.0f;
    if (tid < F_) {
        mval = (float)W_ * __ldg(&h_mask[((b << 6) + tid) * H_ + h]);
    }

    // 2) Front-batched independent coalesced lfi loads (MLP = 7), L2-pinned
    const size_t row0 = (size_t)(b * V_ + wid * 7) * H_ + h;
    float s[7];
    #pragma unroll
    for (int r = 0; r < 7; r++) {
        const float4 v = ld_keep4(&lfi4[(row0 + (size_t)r * H_) * 32 + lane], pl);
        s[r] = (v.x + v.y) + (v.z + v.w);
    }

    // 3) Park mask in smem (overlapped with other warps' reduce)
    if (tid < F_) m_s[tid] = mval;

    // 4) 7 interleaved butterfly reductions (SHFL latency hidden 7-deep)
    #pragma unroll
    for (int o = 16; o > 0; o >>= 1) {
        #pragma unroll
        for (int r = 0; r < 7; r++)
            s[r] += __shfl_xor_sync(0xffffffffu, s[r], o);
    }

    // 5) Barrier after all load latency is absorbed
    __syncthreads();

    // 6) Broadcast mask from smem; evict-first coalesced stores
    const float2 m = ((const float2*)m_s)[lane];
    #pragma unroll
    for (int r = 0; r < 7; r++) {
        st_stream2(&out2[(row0 + (size_t)r * H_) * 32 + lane],
                   s[r] + m.x, s[r] + m.y, pf);
    }
}

extern "C" void kernel_launch(void* const* d_in, const int* in_sizes, int n_in,
                              void* d_out, int out_size) {
    // Identify inputs by element count (robust to ordering):
    //   lfi    : B*V*H*W = 6,422,528
    //   f_maps : B*H*W*F = 8,388,608 (dead input — never touched)
    //   h_mask : B*F*H   = 65,536
    const float* lfi = nullptr;
    const float* h_mask = nullptr;
    for (int i = 0; i < n_in; i++) {
        if (in_sizes[i] == B_ * V_ * H_ * W_) lfi = (const float*)d_in[i];
        else if (in_sizes[i] == B_ * F_ * H_) h_mask = (const float*)d_in[i];
    }

    // 1024 blocks (one per (b,h) pair), 224 threads (7 warps x 7 rows = 49 = V)
    depth_cue_kernel<<<B_ * H_, 224>>>((const float4*)lfi, h_mask, (float2*)d_out);
}